// round 3
// baseline (speedup 1.0000x reference)
#include <cuda_runtime.h>
#include <math.h>

#define Bz 2
#define Sq 2048
#define Dm 1024
#define Hn 16
#define DH 64
#define NREL 129
#define BHN (Bz*Hn)

// scratch for projected Q,K,V in head-split layout [(b*H+h), s, d]
__device__ float g_Q[BHN * Sq * DH];
__device__ float g_K[BHN * Sq * DH];
__device__ float g_V[BHN * Sq * DH];

// ---------------------------------------------------------------------------
// Kernel 1: fused QKV projection GEMM
// Y = X @ W + bias   (X:[4096,1024], W:[1024,1024]), head-split store.
// grid (N/64=16, M/64=64, 3), block 256, 64x64x16 tiles, 4x4 per thread.
// ---------------------------------------------------------------------------
__global__ void qkv_proj_kernel(const float* __restrict__ Xq,
                                const float* __restrict__ Xk,
                                const float* __restrict__ Xv,
                                const float* __restrict__ Wq,
                                const float* __restrict__ Wk,
                                const float* __restrict__ Wv,
                                const float* __restrict__ bq,
                                const float* __restrict__ bk,
                                const float* __restrict__ bv)
{
    const float* X; const float* W; const float* bias; float* out;
    if (blockIdx.z == 0)      { X = Xq; W = Wq; bias = bq; out = g_Q; }
    else if (blockIdx.z == 1) { X = Xk; W = Wk; bias = bk; out = g_K; }
    else                      { X = Xv; W = Wv; bias = bv; out = g_V; }

    __shared__ float Xs[64][16];     // [m][kk] — conflict-free store & broadcast read
    __shared__ float Ws[16][65];     // [kk][n] padded

    const int tid = threadIdx.x;
    const int tx = tid & 15;         // 0..15 -> 4 n-cols each
    const int ty = tid >> 4;         // 0..15 -> 4 m-rows each
    const int m0 = blockIdx.y * 64;
    const int n0 = blockIdx.x * 64;

    float acc[4][4] = {};

    for (int k0 = 0; k0 < Dm; k0 += 16) {
        // load X tile: 64 rows x 16 k
        {
            const int kk = tid & 15;
            const int mb = tid >> 4;
            #pragma unroll
            for (int r = 0; r < 4; r++) {
                int m = mb + r * 16;
                Xs[m][kk] = X[(size_t)(m0 + m) * Dm + k0 + kk];
            }
        }
        // load W tile: 16 k x 64 n
        {
            const int n  = tid & 63;
            const int kb = tid >> 6;
            #pragma unroll
            for (int r = 0; r < 4; r++) {
                int kk = kb + r * 4;
                Ws[kk][n] = W[(size_t)(k0 + kk) * Dm + n0 + n];
            }
        }
        __syncthreads();

        #pragma unroll
        for (int kk = 0; kk < 16; kk++) {
            float a[4], bb[4];
            #pragma unroll
            for (int i = 0; i < 4; i++) a[i]  = Xs[ty * 4 + i][kk];
            #pragma unroll
            for (int j = 0; j < 4; j++) bb[j] = Ws[kk][tx * 4 + j];
            #pragma unroll
            for (int i = 0; i < 4; i++)
                #pragma unroll
                for (int j = 0; j < 4; j++)
                    acc[i][j] += a[i] * bb[j];
        }
        __syncthreads();
    }

    // head-split store: out[((b*H+h)*S + s)*DH + d]
    #pragma unroll
    for (int i = 0; i < 4; i++) {
        const int m = m0 + ty * 4 + i;
        const int b = m >> 11;          // / 2048
        const int s = m & 2047;
        #pragma unroll
        for (int j = 0; j < 4; j++) {
            const int n = n0 + tx * 4 + j;
            const int h = n >> 6;
            const int d = n & 63;
            out[(((size_t)(b * Hn + h) * Sq + s) * DH) + d] = acc[i][j] + bias[n];
        }
    }
}

// ---------------------------------------------------------------------------
// Kernel 2: flash attention with relative-position key bias.
// grid (S/64=32, B*H=32), block 256. 64 q-rows per CTA, k tiles of 64.
// bias collapsed to a per-row 129-entry lookup: pb[r][t] = q_r . rel_table[t]
// ---------------------------------------------------------------------------
#define LDP 65      // padded row stride for 64-wide tiles
#define PBL 132     // padded row stride for the 129-entry bias table

extern __shared__ float smem[];

__global__ void attn_kernel(const float* __restrict__ mask,
                            const float* __restrict__ rel_table,
                            float* __restrict__ out)
{
    float* Qs = smem;                    // 64*65
    float* Ks = Qs + 64 * LDP;           // 64*65
    float* Vs = Ks + 64 * LDP;           // 64*65
    float* Ps = Vs + 64 * LDP;           // 64*65
    float* pb = Ps + 64 * LDP;           // 64*132

    const int tid = threadIdx.x;
    const int tx = tid & 15;             // 4 k-cols / d-cols each
    const int ty = tid >> 4;             // 4 q-rows each
    const int bh = blockIdx.y;
    const int b  = bh / Hn;
    const int h  = bh - b * Hn;
    const int q0 = blockIdx.x * 64;

    const float* Qg = g_Q + (size_t)bh * Sq * DH;
    const float* Kg = g_K + (size_t)bh * Sq * DH;
    const float* Vg = g_V + (size_t)bh * Sq * DH;
    const float* maskb = mask + (size_t)b * Sq;

    // load Q tile
    for (int idx = tid; idx < 64 * 64; idx += 256) {
        int r = idx >> 6, d = idx & 63;
        Qs[r * LDP + d] = Qg[(size_t)(q0 + r) * DH + d];
    }
    __syncthreads();

    // bias lookup table: pb[r][t] = sum_d Qs[r][d] * rel_table[t][d]
    for (int idx = tid; idx < 64 * NREL; idx += 256) {
        int r = idx / NREL;
        int t = idx - r * NREL;
        const float* tr = rel_table + t * DH;
        const float* qr = Qs + r * LDP;
        float sum = 0.f;
        #pragma unroll
        for (int d = 0; d < DH; d++) sum += qr[d] * __ldg(&tr[d]);
        pb[r * PBL + t] = sum;
    }

    float m_i[4], l_i[4], o[4][4];
    #pragma unroll
    for (int i = 0; i < 4; i++) {
        m_i[i] = -INFINITY; l_i[i] = 0.f;
        #pragma unroll
        for (int j = 0; j < 4; j++) o[i][j] = 0.f;
    }

    for (int kt = 0; kt < Sq / 64; kt++) {
        __syncthreads();   // prev PV done (and pb ready on first iter)
        const int k0 = kt * 64;
        for (int idx = tid; idx < 64 * 64; idx += 256) {
            int r = idx >> 6, d = idx & 63;
            Ks[r * LDP + d] = Kg[(size_t)(k0 + r) * DH + d];
            Vs[r * LDP + d] = Vg[(size_t)(k0 + r) * DH + d];
        }
        __syncthreads();

        // scores S = Q K^T   (4x4 micro-tile per thread)
        float sv[4][4] = {};
        #pragma unroll 4
        for (int d = 0; d < 64; d++) {
            float a[4], bb[4];
            #pragma unroll
            for (int i = 0; i < 4; i++) a[i]  = Qs[(ty * 4 + i) * LDP + d];
            #pragma unroll
            for (int j = 0; j < 4; j++) bb[j] = Ks[(tx * 4 + j) * LDP + d];
            #pragma unroll
            for (int i = 0; i < 4; i++)
                #pragma unroll
                for (int j = 0; j < 4; j++)
                    sv[i][j] += a[i] * bb[j];
        }

        // bias + scale + mask, local row max
        float mloc[4];
        #pragma unroll
        for (int i = 0; i < 4; i++) {
            const int qg = q0 + ty * 4 + i;
            float mx = -INFINITY;
            #pragma unroll
            for (int j = 0; j < 4; j++) {
                const int kg = k0 + tx * 4 + j;
                int dd = kg - qg;
                dd = dd < -64 ? -64 : (dd > 64 ? 64 : dd);
                float sc = (sv[i][j] + pb[(ty * 4 + i) * PBL + dd + 64]) * 0.125f
                           + maskb[kg];
                sv[i][j] = sc;
                mx = fmaxf(mx, sc);
            }
            mloc[i] = mx;
        }

        // reduce row max across the 16 threads sharing each row
        #pragma unroll
        for (int i = 0; i < 4; i++) {
            #pragma unroll
            for (int off = 8; off; off >>= 1)
                mloc[i] = fmaxf(mloc[i], __shfl_xor_sync(0xffffffffu, mloc[i], off, 16));
        }

        // online softmax update
        #pragma unroll
        for (int i = 0; i < 4; i++) {
            const float mnew  = fmaxf(m_i[i], mloc[i]);
            const float alpha = __expf(m_i[i] - mnew);   // exp(-inf)=0 first tile
            float rs = 0.f;
            #pragma unroll
            for (int j = 0; j < 4; j++) {
                float p = __expf(sv[i][j] - mnew);
                sv[i][j] = p;
                rs += p;
            }
            #pragma unroll
            for (int off = 8; off; off >>= 1)
                rs += __shfl_xor_sync(0xffffffffu, rs, off, 16);
            l_i[i] = l_i[i] * alpha + rs;
            m_i[i] = mnew;
            #pragma unroll
            for (int j = 0; j < 4; j++) o[i][j] *= alpha;
        }

        // stage P to shared
        #pragma unroll
        for (int i = 0; i < 4; i++)
            #pragma unroll
            for (int j = 0; j < 4; j++)
                Ps[(ty * 4 + i) * LDP + tx * 4 + j] = sv[i][j];
        __syncthreads();

        // O += P V  (4 q-rows x 4 d-cols per thread)
        #pragma unroll 4
        for (int k = 0; k < 64; k++) {
            float a[4], bb[4];
            #pragma unroll
            for (int i = 0; i < 4; i++) a[i]  = Ps[(ty * 4 + i) * LDP + k];
            #pragma unroll
            for (int j = 0; j < 4; j++) bb[j] = Vs[k * LDP + tx * 4 + j];
            #pragma unroll
            for (int i = 0; i < 4; i++)
                #pragma unroll
                for (int j = 0; j < 4; j++)
                    o[i][j] += a[i] * bb[j];
        }
    }

    // epilogue: normalize and write [B,S,D]
    #pragma unroll
    for (int i = 0; i < 4; i++) {
        const int qg = q0 + ty * 4 + i;
        const float inv = 1.f / l_i[i];
        #pragma unroll
        for (int j = 0; j < 4; j++) {
            const int dc = tx * 4 + j;
            out[((size_t)(b * Sq + qg)) * Dm + h * DH + dc] = o[i][j] * inv;
        }
    }
}

// ---------------------------------------------------------------------------
// Launch
// ---------------------------------------------------------------------------
extern "C" void kernel_launch(void* const* d_in, const int* in_sizes, int n_in,
                              void* d_out, int out_size)
{
    const float* query = (const float*)d_in[0];
    const float* key   = (const float*)d_in[1];
    const float* value = (const float*)d_in[2];
    const float* mask  = (const float*)d_in[3];
    const float* Wq    = (const float*)d_in[4];
    const float* bq    = (const float*)d_in[5];
    const float* Wk    = (const float*)d_in[6];
    const float* bk    = (const float*)d_in[7];
    const float* Wv    = (const float*)d_in[8];
    const float* bv    = (const float*)d_in[9];
    const float* rel   = (const float*)d_in[10];
    float* out = (float*)d_out;

    (void)in_sizes; (void)n_in; (void)out_size;

    // 4*64*65 + 64*132 floats = 100352 bytes of dynamic smem
    const int ATTN_SMEM = (4 * 64 * LDP + 64 * PBL) * (int)sizeof(float);
    cudaFuncSetAttribute(attn_kernel,
                         cudaFuncAttributeMaxDynamicSharedMemorySize, ATTN_SMEM);

    dim3 gemm_grid(Dm / 64, (Bz * Sq) / 64, 3);
    qkv_proj_kernel<<<gemm_grid, 256>>>(query, key, value, Wq, Wk, Wv, bq, bk, bv);

    dim3 attn_grid(Sq / 64, Bz * Hn);
    attn_kernel<<<attn_grid, 256, ATTN_SMEM>>>(mask, rel, out);
}

// round 4
// speedup vs baseline: 2.1355x; 2.1355x over previous
#include <cuda_runtime.h>
#include <math.h>

#define Bz 2
#define Sq 2048
#define Dm 1024
#define Hn 16
#define DH 64
#define NREL 129
#define BHN (Bz*Hn)

typedef unsigned long long ull;

__device__ float g_Q[BHN * Sq * DH];
__device__ float g_K[BHN * Sq * DH];
__device__ float g_V[BHN * Sq * DH];

__device__ __forceinline__ ull pack2(float lo, float hi) {
    ull r; asm("mov.b64 %0, {%1, %2};" : "=l"(r) : "f"(lo), "f"(hi)); return r;
}
__device__ __forceinline__ float2 unpack2(ull v) {
    float2 r; asm("mov.b64 {%0, %1}, %2;" : "=f"(r.x), "=f"(r.y) : "l"(v)); return r;
}
__device__ __forceinline__ void fma2(ull& a, ull x, ull y) {
    asm("fma.rn.f32x2 %0, %1, %2, %0;" : "+l"(a) : "l"(x), "l"(y));
}
__device__ __forceinline__ ull mul2(ull x, ull y) {
    ull r; asm("mul.rn.f32x2 %0, %1, %2;" : "=l"(r) : "l"(x), "l"(y)); return r;
}

// ---------------------------------------------------------------------------
// Kernel 1: QKV projection. 128x64 tile, k-step 16, 8x4 micro, FFMA2.
// grid (16, 32, 3), block 256.
// ---------------------------------------------------------------------------
__global__ __launch_bounds__(256, 2)
void qkv_proj_kernel(const float* __restrict__ Xq, const float* __restrict__ Xk,
                     const float* __restrict__ Xv,
                     const float* __restrict__ Wq, const float* __restrict__ Wk,
                     const float* __restrict__ Wv,
                     const float* __restrict__ bq, const float* __restrict__ bk,
                     const float* __restrict__ bv)
{
    const float* X; const float* W; const float* bias; float* outp;
    if (blockIdx.z == 0)      { X = Xq; W = Wq; bias = bq; outp = g_Q; }
    else if (blockIdx.z == 1) { X = Xk; W = Wk; bias = bk; outp = g_K; }
    else                      { X = Xv; W = Wv; bias = bv; outp = g_V; }

    __shared__ __align__(16) float Xt[16][132];   // [k][m] transposed
    __shared__ __align__(16) float Ws[16][68];    // [k][n]

    const int tid = threadIdx.x;
    const int tx = tid & 15, ty = tid >> 4;
    const int m0 = blockIdx.y * 128, n0 = blockIdx.x * 64;
    const int xr = tid & 127, xc = (tid >> 7) * 8;
    const int wr = tid >> 4,  wc = (tid & 15) * 4;

    ull acc[8][2];
    #pragma unroll
    for (int i = 0; i < 8; i++) { acc[i][0] = 0ull; acc[i][1] = 0ull; }

    float4 xa = *(const float4*)&X[(size_t)(m0 + xr) * Dm + xc];
    float4 xb = *(const float4*)&X[(size_t)(m0 + xr) * Dm + xc + 4];
    float4 wv = *(const float4*)&W[(size_t)wr * Dm + n0 + wc];

    for (int t = 0; t < 64; t++) {
        Xt[xc + 0][xr] = xa.x; Xt[xc + 1][xr] = xa.y;
        Xt[xc + 2][xr] = xa.z; Xt[xc + 3][xr] = xa.w;
        Xt[xc + 4][xr] = xb.x; Xt[xc + 5][xr] = xb.y;
        Xt[xc + 6][xr] = xb.z; Xt[xc + 7][xr] = xb.w;
        *(float4*)&Ws[wr][wc] = wv;
        __syncthreads();
        if (t < 63) {
            const int k0 = (t + 1) * 16;
            xa = *(const float4*)&X[(size_t)(m0 + xr) * Dm + k0 + xc];
            xb = *(const float4*)&X[(size_t)(m0 + xr) * Dm + k0 + xc + 4];
            wv = *(const float4*)&W[(size_t)(k0 + wr) * Dm + n0 + wc];
        }
        #pragma unroll
        for (int kk = 0; kk < 16; kk++) {
            float4 a0 = *(const float4*)&Xt[kk][ty * 4];
            float4 a1 = *(const float4*)&Xt[kk][64 + ty * 4];
            ulonglong2 bv = *(const ulonglong2*)&Ws[kk][tx * 4];
            ull p;
            p = pack2(a0.x, a0.x); fma2(acc[0][0], p, bv.x); fma2(acc[0][1], p, bv.y);
            p = pack2(a0.y, a0.y); fma2(acc[1][0], p, bv.x); fma2(acc[1][1], p, bv.y);
            p = pack2(a0.z, a0.z); fma2(acc[2][0], p, bv.x); fma2(acc[2][1], p, bv.y);
            p = pack2(a0.w, a0.w); fma2(acc[3][0], p, bv.x); fma2(acc[3][1], p, bv.y);
            p = pack2(a1.x, a1.x); fma2(acc[4][0], p, bv.x); fma2(acc[4][1], p, bv.y);
            p = pack2(a1.y, a1.y); fma2(acc[5][0], p, bv.x); fma2(acc[5][1], p, bv.y);
            p = pack2(a1.z, a1.z); fma2(acc[6][0], p, bv.x); fma2(acc[6][1], p, bv.y);
            p = pack2(a1.w, a1.w); fma2(acc[7][0], p, bv.x); fma2(acc[7][1], p, bv.y);
        }
        __syncthreads();
    }

    float4 bb = *(const float4*)&bias[n0 + tx * 4];
    const int h = n0 >> 6;
    #pragma unroll
    for (int i = 0; i < 8; i++) {
        const int rl = (i < 4) ? (ty * 4 + i) : (64 + ty * 4 + i - 4);
        const int m = m0 + rl, b = m >> 11, s = m & 2047;
        float2 c0 = unpack2(acc[i][0]), c1 = unpack2(acc[i][1]);
        float4 v = make_float4(c0.x + bb.x, c0.y + bb.y, c1.x + bb.z, c1.y + bb.w);
        *(float4*)&outp[((size_t)((b * Hn + h) * Sq + s)) * DH + tx * 4] = v;
    }
}

// ---------------------------------------------------------------------------
// Kernel 2: flash attention, Bq=Bk=64, FFMA2, transposed Q/K tiles,
// register prefetch of next K/V tile. grid (32, 32), block 256.
// ---------------------------------------------------------------------------
#define QT_OFF 0
#define KT_OFF 4352
#define VS_OFF 8704
#define PS_OFF 13056
#define PB_OFF 17408
#define SM_FLOATS 25856   // + pb[64][132]

extern __shared__ __align__(16) float sm[];

__global__ __launch_bounds__(256, 2)
void attn_kernel(const float* __restrict__ mask,
                 const float* __restrict__ rel,
                 float* __restrict__ out)
{
    float* Qt = sm + QT_OFF;      // [d][r] stride 68
    float* Kt = sm + KT_OFF;      // [d][j] stride 68
    float* Vs = sm + VS_OFF;      // [j][dc] stride 68
    float* Ps = sm + PS_OFF;      // [j][r] stride 68
    float* pb = sm + PB_OFF;      // [r][t] stride 132
    float* rel_s = sm + KT_OFF;   // [t][d] stride 68 overlay (pre-loop only)

    const int tid = threadIdx.x;
    const int tx = tid & 15, ty = tid >> 4;
    const int bh = blockIdx.y, b = bh >> 4, h = bh & 15;
    const int q0 = blockIdx.x * 64;

    const float* Qg = g_Q + (size_t)bh * (Sq * DH);
    const float* Kg = g_K + (size_t)bh * (Sq * DH);
    const float* Vg = g_V + (size_t)bh * (Sq * DH);
    const float* maskb = mask + (size_t)b * Sq;

    const int lr = tid & 63;                 // gmem row for tile loads
    const int ld0 = (tid >> 6) * 4;          // base d (c adds 16)

    // stage Q transposed + rel natural
    #pragma unroll
    for (int c = 0; c < 4; c++) {
        int d = ld0 + 16 * c;
        float4 v = *(const float4*)&Qg[(size_t)(q0 + lr) * DH + d];
        Qt[(d + 0) * 68 + lr] = v.x; Qt[(d + 1) * 68 + lr] = v.y;
        Qt[(d + 2) * 68 + lr] = v.z; Qt[(d + 3) * 68 + lr] = v.w;
    }
    for (int i = tid; i < NREL * 16; i += 256) {
        int t = i >> 4, d = (i & 15) * 4;
        float4 v = *(const float4*)&rel[t * DH + d];
        rel_s[t * 68 + d] = v.x; rel_s[t * 68 + d + 1] = v.y;
        rel_s[t * 68 + d + 2] = v.z; rel_s[t * 68 + d + 3] = v.w;
    }
    __syncthreads();

    // prefetch K/V tile 0 into registers (latency hides under pb compute)
    float4 kr[4], vr[4];
    #pragma unroll
    for (int c = 0; c < 4; c++) {
        int d = ld0 + 16 * c;
        kr[c] = *(const float4*)&Kg[(size_t)lr * DH + d];
        vr[c] = *(const float4*)&Vg[(size_t)lr * DH + d];
    }

    // pb[r][t] = q_r . rel_t
    {
        float pacc[4][9];
        #pragma unroll
        for (int i = 0; i < 4; i++)
            #pragma unroll
            for (int tt = 0; tt < 9; tt++) pacc[i][tt] = 0.f;
        for (int d = 0; d < DH; d++) {
            float4 a = *(const float4*)&Qt[d * 68 + ty * 4];
            #pragma unroll
            for (int tt = 0; tt < 9; tt++) {
                int t = tx + 16 * tt;
                if (t < NREL) {
                    float bv = rel_s[t * 68 + d];
                    pacc[0][tt] += a.x * bv; pacc[1][tt] += a.y * bv;
                    pacc[2][tt] += a.z * bv; pacc[3][tt] += a.w * bv;
                }
            }
        }
        #pragma unroll
        for (int tt = 0; tt < 9; tt++) {
            int t = tx + 16 * tt;
            if (t < NREL)
                #pragma unroll
                for (int i = 0; i < 4; i++)
                    pb[(ty * 4 + i) * 132 + t] = pacc[i][tt];
        }
    }

    ull o[4][2];
    float m_i[4], l_i[4];
    #pragma unroll
    for (int i = 0; i < 4; i++) {
        o[i][0] = 0ull; o[i][1] = 0ull; m_i[i] = -INFINITY; l_i[i] = 0.f;
    }

    for (int kt = 0; kt < 32; kt++) {
        __syncthreads();    // prev tile + rel_s/pb writes consumed
        #pragma unroll
        for (int c = 0; c < 4; c++) {
            int d = ld0 + 16 * c;
            Kt[(d + 0) * 68 + lr] = kr[c].x; Kt[(d + 1) * 68 + lr] = kr[c].y;
            Kt[(d + 2) * 68 + lr] = kr[c].z; Kt[(d + 3) * 68 + lr] = kr[c].w;
            *(float4*)&Vs[lr * 68 + d] = vr[c];
        }
        __syncthreads();
        if (kt < 31) {
            const float* Kn = Kg + (size_t)(kt + 1) * 64 * DH;
            const float* Vn = Vg + (size_t)(kt + 1) * 64 * DH;
            #pragma unroll
            for (int c = 0; c < 4; c++) {
                int d = ld0 + 16 * c;
                kr[c] = *(const float4*)&Kn[(size_t)lr * DH + d];
                vr[c] = *(const float4*)&Vn[(size_t)lr * DH + d];
            }
        }
        const int k0 = kt * 64;

        // scores: acc[i] packed over j
        ull acc[4][2];
        #pragma unroll
        for (int i = 0; i < 4; i++) { acc[i][0] = 0ull; acc[i][1] = 0ull; }
        #pragma unroll 8
        for (int d = 0; d < DH; d++) {
            float4 a = *(const float4*)&Qt[d * 68 + ty * 4];
            ulonglong2 bv = *(const ulonglong2*)&Kt[d * 68 + tx * 4];
            ull p;
            p = pack2(a.x, a.x); fma2(acc[0][0], p, bv.x); fma2(acc[0][1], p, bv.y);
            p = pack2(a.y, a.y); fma2(acc[1][0], p, bv.x); fma2(acc[1][1], p, bv.y);
            p = pack2(a.z, a.z); fma2(acc[2][0], p, bv.x); fma2(acc[2][1], p, bv.y);
            p = pack2(a.w, a.w); fma2(acc[3][0], p, bv.x); fma2(acc[3][1], p, bv.y);
        }

        // bias + scale + mask + online softmax
        float4 mk4 = *(const float4*)&maskb[k0 + tx * 4];
        float sv[4][4];
        #pragma unroll
        for (int i = 0; i < 4; i++) {
            const int rg = q0 + ty * 4 + i;
            float2 f0 = unpack2(acc[i][0]), f1 = unpack2(acc[i][1]);
            sv[i][0] = f0.x; sv[i][1] = f0.y; sv[i][2] = f1.x; sv[i][3] = f1.y;
            float mx = -INFINITY;
            #pragma unroll
            for (int j = 0; j < 4; j++) {
                int kg = k0 + tx * 4 + j;
                int dd = kg - rg; dd = dd < -64 ? -64 : (dd > 64 ? 64 : dd);
                float s = (sv[i][j] + pb[(ty * 4 + i) * 132 + dd + 64]) * 0.125f
                          + ((const float*)&mk4)[j];
                sv[i][j] = s; mx = fmaxf(mx, s);
            }
            #pragma unroll
            for (int off = 8; off; off >>= 1)
                mx = fmaxf(mx, __shfl_xor_sync(0xffffffffu, mx, off, 16));
            const float mnew = fmaxf(m_i[i], mx);
            const float alpha = __expf(m_i[i] - mnew);
            float rs = 0.f;
            #pragma unroll
            for (int j = 0; j < 4; j++) {
                float p = __expf(sv[i][j] - mnew);
                sv[i][j] = p; rs += p;
            }
            #pragma unroll
            for (int off = 8; off; off >>= 1)
                rs += __shfl_xor_sync(0xffffffffu, rs, off, 16);
            l_i[i] = l_i[i] * alpha + rs;
            m_i[i] = mnew;
            ull a2 = pack2(alpha, alpha);
            o[i][0] = mul2(o[i][0], a2);
            o[i][1] = mul2(o[i][1], a2);
        }

        // stage P transposed [j][r]
        #pragma unroll
        for (int j = 0; j < 4; j++)
            *(float4*)&Ps[(tx * 4 + j) * 68 + ty * 4] =
                make_float4(sv[0][j], sv[1][j], sv[2][j], sv[3][j]);
        __syncthreads();

        // O += P V, packed over dc
        #pragma unroll 8
        for (int j = 0; j < 64; j++) {
            float4 a = *(const float4*)&Ps[j * 68 + ty * 4];
            ulonglong2 bv = *(const ulonglong2*)&Vs[j * 68 + tx * 4];
            ull p;
            p = pack2(a.x, a.x); fma2(o[0][0], p, bv.x); fma2(o[0][1], p, bv.y);
            p = pack2(a.y, a.y); fma2(o[1][0], p, bv.x); fma2(o[1][1], p, bv.y);
            p = pack2(a.z, a.z); fma2(o[2][0], p, bv.x); fma2(o[2][1], p, bv.y);
            p = pack2(a.w, a.w); fma2(o[3][0], p, bv.x); fma2(o[3][1], p, bv.y);
        }
    }

    #pragma unroll
    for (int i = 0; i < 4; i++) {
        const int qg = q0 + ty * 4 + i;
        const float inv = 1.f / l_i[i];
        float2 c0 = unpack2(o[i][0]), c1 = unpack2(o[i][1]);
        float4 v = make_float4(c0.x * inv, c0.y * inv, c1.x * inv, c1.y * inv);
        *(float4*)&out[((size_t)(b * Sq + qg)) * Dm + h * DH + tx * 4] = v;
    }
}

extern "C" void kernel_launch(void* const* d_in, const int* in_sizes, int n_in,
                              void* d_out, int out_size)
{
    const float* query = (const float*)d_in[0];
    const float* key   = (const float*)d_in[1];
    const float* value = (const float*)d_in[2];
    const float* mask  = (const float*)d_in[3];
    const float* Wq    = (const float*)d_in[4];
    const float* bq    = (const float*)d_in[5];
    const float* Wk    = (const float*)d_in[6];
    const float* bk    = (const float*)d_in[7];
    const float* Wv    = (const float*)d_in[8];
    const float* bv    = (const float*)d_in[9];
    const float* rel   = (const float*)d_in[10];
    float* out = (float*)d_out;
    (void)in_sizes; (void)n_in; (void)out_size;

    const int ATTN_SMEM = SM_FLOATS * (int)sizeof(float);
    cudaFuncSetAttribute(attn_kernel,
                         cudaFuncAttributeMaxDynamicSharedMemorySize, ATTN_SMEM);

    dim3 gemm_grid(Dm / 64, (Bz * Sq) / 128, 3);
    qkv_proj_kernel<<<gemm_grid, 256>>>(query, key, value, Wq, Wk, Wv, bq, bk, bv);

    dim3 attn_grid(Sq / 64, Bz * Hn);
    attn_kernel<<<attn_grid, 256, ATTN_SMEM>>>(mask, rel, out);
}

// round 5
// speedup vs baseline: 2.4308x; 1.1382x over previous
#include <cuda_runtime.h>
#include <math.h>

#define Bz 2
#define Sq 2048
#define Dm 1024
#define Hn 16
#define DH 64
#define NREL 129
#define BHN (Bz*Hn)

typedef unsigned long long ull;

__device__ float g_Q[BHN * Sq * DH];
__device__ float g_K[BHN * Sq * DH];
__device__ float g_V[BHN * Sq * DH];

__device__ __forceinline__ ull pack2(float lo, float hi) {
    ull r; asm("mov.b64 %0, {%1, %2};" : "=l"(r) : "f"(lo), "f"(hi)); return r;
}
__device__ __forceinline__ float2 unpack2(ull v) {
    float2 r; asm("mov.b64 {%0, %1}, %2;" : "=f"(r.x), "=f"(r.y) : "l"(v)); return r;
}
__device__ __forceinline__ void fma2(ull& a, ull x, ull y) {
    asm("fma.rn.f32x2 %0, %1, %2, %0;" : "+l"(a) : "l"(x), "l"(y));
}
__device__ __forceinline__ ull mul2(ull x, ull y) {
    ull r; asm("mul.rn.f32x2 %0, %1, %2;" : "=l"(r) : "l"(x), "l"(y)); return r;
}
__device__ __forceinline__ void cp16(float* dst, const float* src) {
    unsigned a = (unsigned)__cvta_generic_to_shared(dst);
    asm volatile("cp.async.cg.shared.global [%0], [%1], 16;" :: "r"(a), "l"(src) : "memory");
}

// ---------------------------------------------------------------------------
// Kernel 1: QKV projection. 128x128 tile, k-step 16, 8x8 micro, FFMA2.
// grid (8, 32, 3), block 256, 2 CTAs/SM.
// ---------------------------------------------------------------------------
__global__ __launch_bounds__(256, 2)
void qkv_proj_kernel(const float* __restrict__ Xq, const float* __restrict__ Xk,
                     const float* __restrict__ Xv,
                     const float* __restrict__ Wq, const float* __restrict__ Wk,
                     const float* __restrict__ Wv,
                     const float* __restrict__ bq, const float* __restrict__ bk,
                     const float* __restrict__ bv)
{
    const float* X; const float* W; const float* bias; float* outp;
    if (blockIdx.z == 0)      { X = Xq; W = Wq; bias = bq; outp = g_Q; }
    else if (blockIdx.z == 1) { X = Xk; W = Wk; bias = bk; outp = g_K; }
    else                      { X = Xv; W = Wv; bias = bv; outp = g_V; }

    __shared__ __align__(16) float Xs[16][132];   // [k][m] transposed
    __shared__ __align__(16) float Ws[16][132];   // [k][n]

    const int tid = threadIdx.x;
    const int tx = tid & 15, ty = tid >> 4;
    const int m0 = blockIdx.y * 128, n0 = blockIdx.x * 128;
    const int xr = tid & 127, xk = (tid >> 7) * 8;
    const int wr = tid >> 4,  wc = (tid & 15) * 8;

    ull acc[8][4];
    #pragma unroll
    for (int i = 0; i < 8; i++)
        #pragma unroll
        for (int j = 0; j < 4; j++) acc[i][j] = 0ull;

    float4 xa = *(const float4*)&X[(size_t)(m0 + xr) * Dm + xk];
    float4 xb = *(const float4*)&X[(size_t)(m0 + xr) * Dm + xk + 4];
    float4 wa = *(const float4*)&W[(size_t)wr * Dm + n0 + wc];
    float4 wb = *(const float4*)&W[(size_t)wr * Dm + n0 + wc + 4];

    for (int t = 0; t < 64; t++) {
        Xs[xk + 0][xr] = xa.x; Xs[xk + 1][xr] = xa.y;
        Xs[xk + 2][xr] = xa.z; Xs[xk + 3][xr] = xa.w;
        Xs[xk + 4][xr] = xb.x; Xs[xk + 5][xr] = xb.y;
        Xs[xk + 6][xr] = xb.z; Xs[xk + 7][xr] = xb.w;
        *(float4*)&Ws[wr][wc] = wa;
        *(float4*)&Ws[wr][wc + 4] = wb;
        __syncthreads();
        if (t < 63) {
            const int k0 = (t + 1) * 16;
            xa = *(const float4*)&X[(size_t)(m0 + xr) * Dm + k0 + xk];
            xb = *(const float4*)&X[(size_t)(m0 + xr) * Dm + k0 + xk + 4];
            wa = *(const float4*)&W[(size_t)(k0 + wr) * Dm + n0 + wc];
            wb = *(const float4*)&W[(size_t)(k0 + wr) * Dm + n0 + wc + 4];
        }
        #pragma unroll
        for (int kk = 0; kk < 16; kk++) {
            float4 a0 = *(const float4*)&Xs[kk][ty * 8];
            float4 a1 = *(const float4*)&Xs[kk][ty * 8 + 4];
            ulonglong2 b0 = *(const ulonglong2*)&Ws[kk][tx * 4];
            ulonglong2 b1 = *(const ulonglong2*)&Ws[kk][64 + tx * 4];
            ull p;
            p = pack2(a0.x, a0.x); fma2(acc[0][0], p, b0.x); fma2(acc[0][1], p, b0.y); fma2(acc[0][2], p, b1.x); fma2(acc[0][3], p, b1.y);
            p = pack2(a0.y, a0.y); fma2(acc[1][0], p, b0.x); fma2(acc[1][1], p, b0.y); fma2(acc[1][2], p, b1.x); fma2(acc[1][3], p, b1.y);
            p = pack2(a0.z, a0.z); fma2(acc[2][0], p, b0.x); fma2(acc[2][1], p, b0.y); fma2(acc[2][2], p, b1.x); fma2(acc[2][3], p, b1.y);
            p = pack2(a0.w, a0.w); fma2(acc[3][0], p, b0.x); fma2(acc[3][1], p, b0.y); fma2(acc[3][2], p, b1.x); fma2(acc[3][3], p, b1.y);
            p = pack2(a1.x, a1.x); fma2(acc[4][0], p, b0.x); fma2(acc[4][1], p, b0.y); fma2(acc[4][2], p, b1.x); fma2(acc[4][3], p, b1.y);
            p = pack2(a1.y, a1.y); fma2(acc[5][0], p, b0.x); fma2(acc[5][1], p, b0.y); fma2(acc[5][2], p, b1.x); fma2(acc[5][3], p, b1.y);
            p = pack2(a1.z, a1.z); fma2(acc[6][0], p, b0.x); fma2(acc[6][1], p, b0.y); fma2(acc[6][2], p, b1.x); fma2(acc[6][3], p, b1.y);
            p = pack2(a1.w, a1.w); fma2(acc[7][0], p, b0.x); fma2(acc[7][1], p, b0.y); fma2(acc[7][2], p, b1.x); fma2(acc[7][3], p, b1.y);
        }
        __syncthreads();
    }

    float4 bl = *(const float4*)&bias[n0 + tx * 4];
    float4 bh = *(const float4*)&bias[n0 + 64 + tx * 4];
    const int h0 = n0 >> 6;
    #pragma unroll
    for (int i = 0; i < 8; i++) {
        const int m = m0 + ty * 8 + i, bb = m >> 11, s = m & 2047;
        float2 c0 = unpack2(acc[i][0]), c1 = unpack2(acc[i][1]);
        float4 v = make_float4(c0.x + bl.x, c0.y + bl.y, c1.x + bl.z, c1.y + bl.w);
        *(float4*)&outp[((size_t)((bb * Hn + h0) * Sq + s)) * DH + tx * 4] = v;
        c0 = unpack2(acc[i][2]); c1 = unpack2(acc[i][3]);
        v = make_float4(c0.x + bh.x, c0.y + bh.y, c1.x + bh.z, c1.y + bh.w);
        *(float4*)&outp[((size_t)((bb * Hn + h0 + 1) * Sq + s)) * DH + tx * 4] = v;
    }
}

// ---------------------------------------------------------------------------
// Kernel 2: flash attention, Bq=128, Bk=64, 8x4 micro FFMA2.
// grid (16, 32), block 256, 1 CTA/SM.
// ---------------------------------------------------------------------------
#define QT 0        // [64][136] Q transposed [d][r]
#define KT 8704     // [64][68]  K transposed [d][j]
#define VS 13056    // [2][64][68] V natural [j][dc]
#define PS 21760    // [64][128] P transposed [j][r], XOR-swizzled units
#define PB 29952    // [128][132] bias lookup
#define SMF 46848

extern __shared__ __align__(16) float sm[];

__global__ __launch_bounds__(256, 1)
void attn_kernel(const float* __restrict__ mask,
                 const float* __restrict__ rel,
                 float* __restrict__ out)
{
    float* Qt = sm + QT;
    float* Kt = sm + KT;
    float* Vs = sm + VS;
    float* Ps = sm + PS;
    float* pb = sm + PB;
    float* relT = sm + KT;   // [64][144] overlay, dead after pb compute

    const int tid = threadIdx.x;
    const int tx = tid & 15, ty = tid >> 4;
    const int bh = blockIdx.y, b = bh >> 4, h = bh & 15;
    const int q0 = blockIdx.x * 128;

    const float* Qg = g_Q + (size_t)bh * (Sq * DH);
    const float* Kg = g_K + (size_t)bh * (Sq * DH);
    const float* Vg = g_V + (size_t)bh * (Sq * DH);
    const float* maskb = mask + (size_t)b * Sq;

    // ---- stage Q transposed ----
    {
        const int qr = tid & 127, qc = (tid >> 7) * 32;
        #pragma unroll
        for (int u = 0; u < 8; u++) {
            int d = qc + u * 4;
            float4 v = *(const float4*)&Qg[(size_t)(q0 + qr) * DH + d];
            Qt[(d + 0) * 136 + qr] = v.x; Qt[(d + 1) * 136 + qr] = v.y;
            Qt[(d + 2) * 136 + qr] = v.z; Qt[(d + 3) * 136 + qr] = v.w;
        }
    }
    // ---- stage rel transposed [d][t], zero-pad t in [129,144) ----
    for (int i = tid; i < 64 * 15; i += 256)
        relT[(i / 15) * 144 + 129 + (i % 15)] = 0.f;
    for (int i = tid; i < NREL * 16; i += 256) {
        int t = i >> 4, d4 = (i & 15) * 4;
        float4 v = *(const float4*)&rel[t * DH + d4];
        relT[(d4 + 0) * 144 + t] = v.x; relT[(d4 + 1) * 144 + t] = v.y;
        relT[(d4 + 2) * 144 + t] = v.z; relT[(d4 + 3) * 144 + t] = v.w;
    }
    __syncthreads();

    // ---- pb[r][t] = q_r . rel_t  (rows packed in f32x2) ----
    {
        ull pa[4][9];
        #pragma unroll
        for (int rp = 0; rp < 4; rp++)
            #pragma unroll
            for (int tt = 0; tt < 9; tt++) pa[rp][tt] = 0ull;
        for (int d = 0; d < DH; d++) {
            ulonglong2 qa = *(const ulonglong2*)&Qt[d * 136 + ty * 8];
            ulonglong2 qb = *(const ulonglong2*)&Qt[d * 136 + ty * 8 + 4];
            #pragma unroll
            for (int tt = 0; tt < 9; tt++) {
                float rv = relT[d * 144 + tx + 16 * tt];
                ull rv2 = pack2(rv, rv);
                fma2(pa[0][tt], qa.x, rv2); fma2(pa[1][tt], qa.y, rv2);
                fma2(pa[2][tt], qb.x, rv2); fma2(pa[3][tt], qb.y, rv2);
            }
        }
        #pragma unroll
        for (int tt = 0; tt < 9; tt++) {
            int t = tx + 16 * tt;
            if (t < 132) {
                #pragma unroll
                for (int rp = 0; rp < 4; rp++) {
                    float2 f = unpack2(pa[rp][tt]);
                    pb[(ty * 8 + 2 * rp)     * 132 + t] = f.x;
                    pb[(ty * 8 + 2 * rp + 1) * 132 + t] = f.y;
                }
            }
        }
    }
    __syncthreads();

    // constant-clip biases per row
    float pLo[8], pHi[8];
    #pragma unroll
    for (int i = 0; i < 8; i++) {
        pLo[i] = pb[(ty * 8 + i) * 132];
        pHi[i] = pb[(ty * 8 + i) * 132 + 128];
    }

    // ---- prologue loads: V0 via cp.async, K0 via LDG ----
    const int krow = tid & 63, kd0 = (tid >> 6) * 16;
    #pragma unroll
    for (int c = 0; c < 4; c++)
        cp16(&Vs[krow * 68 + kd0 + 4 * c], &Vg[(size_t)krow * DH + kd0 + 4 * c]);
    asm volatile("cp.async.commit_group;" ::: "memory");
    float4 kr4[4];
    #pragma unroll
    for (int c = 0; c < 4; c++)
        kr4[c] = *(const float4*)&Kg[(size_t)krow * DH + kd0 + 4 * c];

    ull o[8][2];
    float m_i[8], l_i[8];
    #pragma unroll
    for (int i = 0; i < 8; i++) {
        o[i][0] = 0ull; o[i][1] = 0ull; m_i[i] = -INFINITY; l_i[i] = 0.f;
    }

    for (int kt = 0; kt < 32; kt++) {
        const int buf = kt & 1;
        const int k0 = kt * 64;
        __syncthreads();   // prev tile consumers done

        #pragma unroll
        for (int c = 0; c < 4; c++) {
            int d = kd0 + 4 * c;
            Kt[(d + 0) * 68 + krow] = kr4[c].x; Kt[(d + 1) * 68 + krow] = kr4[c].y;
            Kt[(d + 2) * 68 + krow] = kr4[c].z; Kt[(d + 3) * 68 + krow] = kr4[c].w;
        }
        if (kt < 31) {
            const float* Vn = Vg + (size_t)(k0 + 64) * DH;
            const float* Kn = Kg + (size_t)(k0 + 64) * DH;
            float* Vd = Vs + (buf ^ 1) * 4352;
            #pragma unroll
            for (int c = 0; c < 4; c++)
                cp16(&Vd[krow * 68 + kd0 + 4 * c], &Vn[(size_t)krow * DH + kd0 + 4 * c]);
            asm volatile("cp.async.commit_group;" ::: "memory");
            #pragma unroll
            for (int c = 0; c < 4; c++)
                kr4[c] = *(const float4*)&Kn[(size_t)krow * DH + kd0 + 4 * c];
            asm volatile("cp.async.wait_group 1;" ::: "memory");
        } else {
            asm volatile("cp.async.wait_group 0;" ::: "memory");
        }
        __syncthreads();   // Kt + Vs[buf] visible

        // ---- scores ----
        ull acc[8][2];
        #pragma unroll
        for (int i = 0; i < 8; i++) { acc[i][0] = 0ull; acc[i][1] = 0ull; }
        #pragma unroll 4
        for (int d = 0; d < DH; d++) {
            float4 a0 = *(const float4*)&Qt[d * 136 + ty * 8];
            float4 a1 = *(const float4*)&Qt[d * 136 + ty * 8 + 4];
            ulonglong2 bv = *(const ulonglong2*)&Kt[d * 68 + tx * 4];
            ull p;
            p = pack2(a0.x, a0.x); fma2(acc[0][0], p, bv.x); fma2(acc[0][1], p, bv.y);
            p = pack2(a0.y, a0.y); fma2(acc[1][0], p, bv.x); fma2(acc[1][1], p, bv.y);
            p = pack2(a0.z, a0.z); fma2(acc[2][0], p, bv.x); fma2(acc[2][1], p, bv.y);
            p = pack2(a0.w, a0.w); fma2(acc[3][0], p, bv.x); fma2(acc[3][1], p, bv.y);
            p = pack2(a1.x, a1.x); fma2(acc[4][0], p, bv.x); fma2(acc[4][1], p, bv.y);
            p = pack2(a1.y, a1.y); fma2(acc[5][0], p, bv.x); fma2(acc[5][1], p, bv.y);
            p = pack2(a1.z, a1.z); fma2(acc[6][0], p, bv.x); fma2(acc[6][1], p, bv.y);
            p = pack2(a1.w, a1.w); fma2(acc[7][0], p, bv.x); fma2(acc[7][1], p, bv.y);
        }

        // ---- softmax ----
        float4 mk4 = *(const float4*)&maskb[k0 + tx * 4];
        const float mkf[4] = {mk4.x, mk4.y, mk4.z, mk4.w};
        const int ddmin = k0 - (q0 + 127), ddmax = k0 + 63 - q0;
        const bool gen = (ddmax > -64) && (ddmin < 64);
        float pv[8][4];
        #pragma unroll
        for (int i = 0; i < 8; i++) {
            float2 f0 = unpack2(acc[i][0]), f1 = unpack2(acc[i][1]);
            float s[4] = {f0.x, f0.y, f1.x, f1.y};
            if (gen) {
                const int rg = q0 + ty * 8 + i;
                #pragma unroll
                for (int jj = 0; jj < 4; jj++) {
                    int dd = k0 + tx * 4 + jj - rg;
                    dd = dd < -64 ? -64 : (dd > 64 ? 64 : dd);
                    s[jj] = (s[jj] + pb[(ty * 8 + i) * 132 + dd + 64]) * 0.125f + mkf[jj];
                }
            } else {
                const float bi = (ddmin >= 64) ? pHi[i] : pLo[i];
                #pragma unroll
                for (int jj = 0; jj < 4; jj++)
                    s[jj] = (s[jj] + bi) * 0.125f + mkf[jj];
            }
            float mx = fmaxf(fmaxf(s[0], s[1]), fmaxf(s[2], s[3]));
            #pragma unroll
            for (int off = 8; off; off >>= 1)
                mx = fmaxf(mx, __shfl_xor_sync(0xffffffffu, mx, off, 16));
            const float mnew = fmaxf(m_i[i], mx);
            const float alpha = __expf(m_i[i] - mnew);
            float rs = 0.f;
            #pragma unroll
            for (int jj = 0; jj < 4; jj++) {
                float p = __expf(s[jj] - mnew);
                pv[i][jj] = p; rs += p;
            }
            #pragma unroll
            for (int off = 8; off; off >>= 1)
                rs += __shfl_xor_sync(0xffffffffu, rs, off, 16);
            l_i[i] = l_i[i] * alpha + rs;
            m_i[i] = mnew;
            ull a2 = pack2(alpha, alpha);
            o[i][0] = mul2(o[i][0], a2);
            o[i][1] = mul2(o[i][1], a2);
        }

        // ---- stage P transposed with unit swizzle ----
        {
            const int swz = tx & 7;
            #pragma unroll
            for (int jj = 0; jj < 4; jj++) {
                float* bp = Ps + (tx * 4 + jj) * 128;
                *(float4*)(bp + 4 * ((2 * ty) ^ swz)) =
                    make_float4(pv[0][jj], pv[1][jj], pv[2][jj], pv[3][jj]);
                *(float4*)(bp + 4 * ((2 * ty + 1) ^ swz)) =
                    make_float4(pv[4][jj], pv[5][jj], pv[6][jj], pv[7][jj]);
            }
        }
        __syncthreads();

        // ---- O += P V ----
        const float* Vb = Vs + buf * 4352;
        #pragma unroll 4
        for (int j = 0; j < 64; j++) {
            const int swz = (j >> 2) & 7;
            float4 a0 = *(const float4*)(Ps + j * 128 + 4 * ((2 * ty) ^ swz));
            float4 a1 = *(const float4*)(Ps + j * 128 + 4 * ((2 * ty + 1) ^ swz));
            ulonglong2 bv = *(const ulonglong2*)&Vb[j * 68 + tx * 4];
            ull p;
            p = pack2(a0.x, a0.x); fma2(o[0][0], p, bv.x); fma2(o[0][1], p, bv.y);
            p = pack2(a0.y, a0.y); fma2(o[1][0], p, bv.x); fma2(o[1][1], p, bv.y);
            p = pack2(a0.z, a0.z); fma2(o[2][0], p, bv.x); fma2(o[2][1], p, bv.y);
            p = pack2(a0.w, a0.w); fma2(o[3][0], p, bv.x); fma2(o[3][1], p, bv.y);
            p = pack2(a1.x, a1.x); fma2(o[4][0], p, bv.x); fma2(o[4][1], p, bv.y);
            p = pack2(a1.y, a1.y); fma2(o[5][0], p, bv.x); fma2(o[5][1], p, bv.y);
            p = pack2(a1.z, a1.z); fma2(o[6][0], p, bv.x); fma2(o[6][1], p, bv.y);
            p = pack2(a1.w, a1.w); fma2(o[7][0], p, bv.x); fma2(o[7][1], p, bv.y);
        }
    }

    #pragma unroll
    for (int i = 0; i < 8; i++) {
        const int qg = q0 + ty * 8 + i;
        const float inv = 1.f / l_i[i];
        float2 c0 = unpack2(o[i][0]), c1 = unpack2(o[i][1]);
        float4 v = make_float4(c0.x * inv, c0.y * inv, c1.x * inv, c1.y * inv);
        *(float4*)&out[((size_t)(b * Sq + qg)) * Dm + h * DH + tx * 4] = v;
    }
}

extern "C" void kernel_launch(void* const* d_in, const int* in_sizes, int n_in,
                              void* d_out, int out_size)
{
    const float* query = (const float*)d_in[0];
    const float* key   = (const float*)d_in[1];
    const float* value = (const float*)d_in[2];
    const float* mask  = (const float*)d_in[3];
    const float* Wq    = (const float*)d_in[4];
    const float* bq    = (const float*)d_in[5];
    const float* Wk    = (const float*)d_in[6];
    const float* bk    = (const float*)d_in[7];
    const float* Wv    = (const float*)d_in[8];
    const float* bv    = (const float*)d_in[9];
    const float* rel   = (const float*)d_in[10];
    float* out = (float*)d_out;
    (void)in_sizes; (void)n_in; (void)out_size;

    const int ATTN_SMEM = SMF * (int)sizeof(float);
    cudaFuncSetAttribute(attn_kernel,
                         cudaFuncAttributeMaxDynamicSharedMemorySize, ATTN_SMEM);

    dim3 gemm_grid(Dm / 128, (Bz * Sq) / 128, 3);
    qkv_proj_kernel<<<gemm_grid, 256>>>(query, key, value, Wq, Wk, Wv, bq, bk, bv);

    dim3 attn_grid(Sq / 128, Bz * Hn);
    attn_kernel<<<attn_grid, 256, ATTN_SMEM>>>(mask, rel, out);
}